// round 1
// baseline (speedup 1.0000x reference)
#include <cuda_runtime.h>
#include <cuda_bf16.h>

// Shapes (fixed for this problem)
#define B_   32
#define P_   16
#define S_   256
#define D_   256
#define NG_  128
#define N_   4096      // B*NG
#define E_   65536
#define H_   256

// ---------------- scratch (static device globals; no allocation allowed) ----
__device__ float g_node_x[N_ * D_];
__device__ float g_deg[N_];
__device__ float g_dis[N_];
__device__ int   g_cnt[N_];
__device__ int   g_cursor[N_];
__device__ int   g_offs[N_ + 1];
__device__ int   g_csr_src[E_];
__device__ float g_csr_w[E_];
__device__ float g_agg[N_ * D_];
__device__ float g_x1[N_ * H_];
__device__ float g_C[N_ * B_];      // c[u][b] = sum of norms of edges u->v with v in graph b
__device__ float g_tmp[B_ * D_];    // pooled pre-W2 activations

// ---------------- kernels ---------------------------------------------------

// zero cnt/cursor/C/tmp, deg = 1 (self loop)
__global__ void k_init() {
    int i = blockIdx.x * blockDim.x + threadIdx.x;
    if (i < N_) { g_cnt[i] = 0; g_cursor[i] = 0; g_deg[i] = 1.0f; }
    if (i < N_ * B_) g_C[i] = 0.0f;
    if (i < B_ * D_) g_tmp[i] = 0.0f;
}

// node_x[n][d] = mean_p dge[b, p, gid[n], d]   (gather-then-mean: reads only needed rows)
__global__ void k_node_mean(const float* __restrict__ dge, const int* __restrict__ gids) {
    int n = blockIdx.x;
    int d = threadIdx.x;
    int b = n >> 7;                 // n / NG_
    int g = gids[n];
    const float* base = dge + ((size_t)b * P_ * S_ + g) * D_ + d;
    float s = 0.0f;
#pragma unroll
    for (int p = 0; p < P_; p++) s += base[(size_t)p * S_ * D_];
    g_node_x[n * D_ + d] = s * (1.0f / P_);
}

// degree (+1 self already in init) and per-dst histogram
__global__ void k_deg_count(const int* __restrict__ ei) {
    int e = blockIdx.x * blockDim.x + threadIdx.x;
    if (e < E_) {
        int v = ei[E_ + e];          // dst
        atomicAdd(&g_deg[v], 1.0f);
        atomicAdd(&g_cnt[v], 1);
    }
}

// dis = rsqrt(deg); seed C with self-loop contribution c[v][graph(v)] += dis[v]^2
__global__ void k_dis() {
    int n = blockIdx.x * blockDim.x + threadIdx.x;
    if (n < N_) {
        float dv = rsqrtf(g_deg[n]);
        g_dis[n] = dv;
        g_C[n * B_ + (n >> 7)] = dv * dv;   // C zeroed before; only this thread writes it here
    }
}

// exclusive scan over cnt[4096] -> offs[4097], single block of 1024 threads, 4 elems each
__global__ void k_scan() {
    __shared__ int s[1024];
    int t = threadIdx.x;
    int v0 = g_cnt[t * 4 + 0], v1 = g_cnt[t * 4 + 1], v2 = g_cnt[t * 4 + 2], v3 = g_cnt[t * 4 + 3];
    int local = v0 + v1 + v2 + v3;
    s[t] = local;
    __syncthreads();
    for (int off = 1; off < 1024; off <<= 1) {
        int x = (t >= off) ? s[t - off] : 0;
        __syncthreads();
        s[t] += x;
        __syncthreads();
    }
    int excl = s[t] - local;
    g_offs[t * 4 + 0] = excl;
    g_offs[t * 4 + 1] = excl + v0;
    g_offs[t * 4 + 2] = excl + v0 + v1;
    g_offs[t * 4 + 3] = excl + v0 + v1 + v2;
    if (t == 1023) g_offs[N_] = s[1023];
}

// scatter edges into CSR (by dst), compute norm, and accumulate C[u][graph(dst)]
__global__ void k_scatter(const int* __restrict__ ei) {
    int e = blockIdx.x * blockDim.x + threadIdx.x;
    if (e < E_) {
        int u = ei[e];
        int v = ei[E_ + e];
        float w = g_dis[u] * g_dis[v];
        int pos = g_offs[v] + atomicAdd(&g_cursor[v], 1);
        g_csr_src[pos] = u;
        g_csr_w[pos] = w;
        atomicAdd(&g_C[u * B_ + (v >> 7)], w);
    }
}

// agg[v] = dis[v]^2 * node_x[v] + sum_{u->v} norm * node_x[u]   (gather, no atomics)
__global__ void k_aggregate() {
    __shared__ int   ssrc[256];
    __shared__ float sw[256];
    int v = blockIdx.x;
    int d = threadIdx.x;
    int beg = g_offs[v];
    int end = g_offs[v + 1];
    float dv = g_dis[v];
    float acc = dv * dv * g_node_x[v * D_ + d];
    for (int base = beg; base < end; base += 256) {
        int nn = end - base; if (nn > 256) nn = 256;
        if (d < nn) { ssrc[d] = g_csr_src[base + d]; sw[d] = g_csr_w[base + d]; }
        __syncthreads();
        float a0 = 0.f, a1 = 0.f, a2 = 0.f, a3 = 0.f;
        int i = 0;
        for (; i + 4 <= nn; i += 4) {
            a0 += sw[i + 0] * g_node_x[ssrc[i + 0] * D_ + d];
            a1 += sw[i + 1] * g_node_x[ssrc[i + 1] * D_ + d];
            a2 += sw[i + 2] * g_node_x[ssrc[i + 2] * D_ + d];
            a3 += sw[i + 3] * g_node_x[ssrc[i + 3] * D_ + d];
        }
        for (; i < nn; i++) a0 += sw[i] * g_node_x[ssrc[i] * D_ + d];
        acc += (a0 + a1) + (a2 + a3);
        __syncthreads();
    }
    g_agg[v * D_ + d] = acc;
}

// x1 = relu(agg @ W1 + b1); M=4096, K=256, N=256; 64x64 tile, 4x4 per thread
__global__ void k_gemm_relu(const float* __restrict__ W, const float* __restrict__ bias) {
    __shared__ float As[16][68];   // [k][m], padded row stride (aligned for float4)
    __shared__ float Bs[16][64];   // [k][n]
    int tid = threadIdx.x;
    int m0 = blockIdx.x * 64, n0 = blockIdx.y * 64;
    int tx = tid & 15, ty = tid >> 4;
    float acc[4][4] = {};
    for (int k0 = 0; k0 < 256; k0 += 16) {
        {   // load A tile 64x16 (transposed into As)
            int row = tid >> 2;            // 0..63
            int kq  = (tid & 3) << 2;      // 0,4,8,12
            float4 a = *(const float4*)&g_agg[(m0 + row) * 256 + k0 + kq];
            As[kq + 0][row] = a.x; As[kq + 1][row] = a.y;
            As[kq + 2][row] = a.z; As[kq + 3][row] = a.w;
        }
        {   // load B tile 16x64
            int row = tid >> 4;            // 0..15
            int nq  = (tid & 15) << 2;     // 0..60
            float4 b = *(const float4*)&W[(k0 + row) * 256 + n0 + nq];
            *(float4*)&Bs[row][nq] = b;
        }
        __syncthreads();
#pragma unroll
        for (int kk = 0; kk < 16; kk++) {
            float4 av = *(const float4*)&As[kk][ty * 4];
            float4 bv = *(const float4*)&Bs[kk][tx * 4];
            acc[0][0] += av.x * bv.x; acc[0][1] += av.x * bv.y; acc[0][2] += av.x * bv.z; acc[0][3] += av.x * bv.w;
            acc[1][0] += av.y * bv.x; acc[1][1] += av.y * bv.y; acc[1][2] += av.y * bv.z; acc[1][3] += av.y * bv.w;
            acc[2][0] += av.z * bv.x; acc[2][1] += av.z * bv.y; acc[2][2] += av.z * bv.z; acc[2][3] += av.z * bv.w;
            acc[3][0] += av.w * bv.x; acc[3][1] += av.w * bv.y; acc[3][2] += av.w * bv.z; acc[3][3] += av.w * bv.w;
        }
        __syncthreads();
    }
#pragma unroll
    for (int i = 0; i < 4; i++) {
        int m = m0 + ty * 4 + i;
#pragma unroll
        for (int j = 0; j < 4; j++) {
            int nc = n0 + tx * 4 + j;
            float vv = acc[i][j] + bias[nc];
            g_x1[m * 256 + nc] = fmaxf(vv, 0.0f);
        }
    }
}

// tmp[b][d] += sum_{u in block's range} C[u][b] * x1[u][d]   (64 u-rows per block)
__global__ void k_pool_partial() {
    __shared__ float sC[64][32];
    int t = threadIdx.x;
    int u0 = blockIdx.x * 64;
    for (int i = t; i < 64 * 32; i += 256) sC[i >> 5][i & 31] = g_C[u0 * 32 + i];
    __syncthreads();
    float acc[32];
#pragma unroll
    for (int b = 0; b < 32; b++) acc[b] = 0.0f;
    int d = t;  // 256 threads = one column each
    for (int uu = 0; uu < 64; uu++) {
        float x = g_x1[(u0 + uu) * 256 + d];
#pragma unroll
        for (int b = 0; b < 32; b++) acc[b] += sC[uu][b] * x;
    }
#pragma unroll
    for (int b = 0; b < 32; b++) atomicAdd(&g_tmp[b * 256 + d], acc[b]);
}

// out[b][h] = (1/NG) * (tmp[b] @ W2)[h] + b2[h]
__global__ void k_final(const float* __restrict__ W2, const float* __restrict__ b2,
                        float* __restrict__ out) {
    int b = blockIdx.x, h = threadIdx.x;
    float acc = 0.0f;
    const float* trow = &g_tmp[b * 256];
#pragma unroll 4
    for (int d = 0; d < 256; d++) acc += trow[d] * W2[d * 256 + h];
    out[b * 256 + h] = acc * (1.0f / NG_) + b2[h];
}

// ---------------- launch -----------------------------------------------------
extern "C" void kernel_launch(void* const* d_in, const int* in_sizes, int n_in,
                              void* d_out, int out_size) {
    const float* dge  = (const float*)d_in[0];  // [B,P,S,D]
    const int*   gids = (const int*)  d_in[1];  // [B,NG]
    const int*   ei   = (const int*)  d_in[2];  // [2,E]
    const float* W1   = (const float*)d_in[3];  // [D,H]
    const float* b1   = (const float*)d_in[4];  // [H]
    const float* W2   = (const float*)d_in[5];  // [H,H]
    const float* b2   = (const float*)d_in[6];  // [H]
    float* out = (float*)d_out;                 // [B,H]

    k_init<<<(N_ * B_ + 255) / 256, 256>>>();
    k_node_mean<<<N_, D_>>>(dge, gids);
    k_deg_count<<<E_ / 256, 256>>>(ei);
    k_dis<<<N_ / 256, 256>>>();
    k_scan<<<1, 1024>>>();
    k_scatter<<<E_ / 256, 256>>>(ei);
    k_aggregate<<<N_, 256>>>();
    k_gemm_relu<<<dim3(N_ / 64, H_ / 64), 256>>>(W1, b1);
    k_pool_partial<<<N_ / 64, 256>>>();
    k_final<<<B_, H_>>>(W2, b2, out);
}